// round 7
// baseline (speedup 1.0000x reference)
#include <cuda_runtime.h>
#include <cuda_bf16.h>
#include <cstdint>

#define DDIM   512
#define MPTS   131072
#define BQ     64
#define BLOCK_M 128
#define KC     64
#define NCHUNK (DDIM / KC)         // 8
#define NTILES (MPTS / BLOCK_M)    // 1024
#define GRID   148

#define VSTRIDE 520                // bf16 elems per b-row in smem (bank-safe)
#define ASTRIDE 132                // int32 elems per k-row in smem (bank-safe, 16B-aligned rows)

// -------------------- device globals (allocation-free scratch) --------------------
__device__ __nv_bfloat16 g_V[BQ * DDIM];   // [b][d], V[d][b] = W[d]*(1-2*x1[d][b])
__device__ float g_s1[BQ];
__device__ float g_norm;
__device__ float g_acc[BQ];

// -------------------- prep: V (bf16), s1, norm, zero acc --------------------
__global__ void knn_prep(const int* __restrict__ X1, const float* __restrict__ W)
{
    __shared__ float s1_sm[BQ];
    __shared__ float nrm_sm;
    const int tid = threadIdx.x;   // 256 threads

    if (tid < BQ) { s1_sm[tid] = 0.f; g_acc[tid] = 0.f; }
    if (tid == 0) nrm_sm = 0.f;
    __syncthreads();

    // V[b][d] = +-W[d]
    for (int idx = tid; idx < DDIM * BQ; idx += 256) {
        int d = idx >> 6, b = idx & 63;
        float w = W[d];
        int x1 = X1[d * BQ + b];
        g_V[b * DDIM + d] = __float2bfloat16(x1 ? -w : w);
    }

    // s1[b] = sum_d W[d]*x1[d][b]  (4 partials per b)
    {
        int b = tid & 63, part = tid >> 6;
        float s = 0.f;
        for (int d = part * 128; d < part * 128 + 128; d++)
            s += W[d] * (float)X1[d * BQ + b];
        atomicAdd(&s1_sm[b], s);
    }
    // norm = sum |W| + eps
    {
        float s = fabsf(W[tid * 2]) + fabsf(W[tid * 2 + 1]);
        atomicAdd(&nrm_sm, s);
    }
    __syncthreads();
    if (tid < BQ) g_s1[tid] = s1_sm[tid];
    if (tid == 0) g_norm = nrm_sm + 1e-6f;
}

// -------------------- squash F --------------------
__device__ __forceinline__ float squashF(float x, float kk, float jj)
{
    float inner = x * (1.f - kk) / (kk * (1.f - 2.f * fabsf(x)) + 1.f);
    float t = 2.f * inner - 1.f;
    return 0.5f + 0.5f * t * (1.f + jj) / (-jj * (1.f - 2.f * fabsf(t)) + 1.f);
}

__device__ __forceinline__ void mma_bf16(float c[4], const uint32_t a[4], const uint32_t b[2])
{
    asm volatile(
        "mma.sync.aligned.m16n8k16.row.col.f32.bf16.bf16.f32 "
        "{%0,%1,%2,%3}, {%4,%5,%6,%7}, {%8,%9}, {%0,%1,%2,%3};\n"
        : "+f"(c[0]), "+f"(c[1]), "+f"(c[2]), "+f"(c[3])
        : "r"(a[0]), "r"(a[1]), "r"(a[2]), "r"(a[3]), "r"(b[0]), "r"(b[1]));
}

// -------------------- main: fused int32->bf16 GEMM + squash + reduce --------------------
__global__ void __launch_bounds__(256, 1) knn_main(
    const int*   __restrict__ X2,   // [DDIM][MPTS] 0/1 ints
    const float* __restrict__ Y,    // [MPTS]
    const float* __restrict__ kp,
    const float* __restrict__ jp)
{
    extern __shared__ char smem[];
    __nv_bfloat16* V_s = (__nv_bfloat16*)smem;                       // 64*520*2 = 66560 B
    int* A_s0 = (int*)(smem + BQ * VSTRIDE * 2);                     // 64*132*4 = 33792 B
    int* A_s1 = A_s0 + KC * ASTRIDE;                                 // 33792 B
    float* s1_s  = (float*)(smem + BQ * VSTRIDE * 2 + 2 * KC * ASTRIDE * 4);
    float* s_acc = s1_s + BQ;

    const int tid  = threadIdx.x;
    const int lane = tid & 31, warp = tid >> 5;
    const int g = lane >> 2, tig = lane & 3;
    const int wm = warp & 3, wb = warp >> 2;     // 4 m-strips x 2 b-halves

    // Stage full V into smem (pitched), s1, zero partial accumulators
    for (int idx = tid; idx < BQ * DDIM; idx += 256) {
        int b = idx >> 9, d = idx & (DDIM - 1);
        V_s[b * VSTRIDE + d] = g_V[idx];
    }
    if (tid < BQ) { s1_s[tid] = g_s1[tid]; s_acc[tid] = 0.f; }
    const float inv_norm = 1.f / g_norm;
    const float kk = kp[0], jj = jp[0];

    const int ntile = (NTILES - (int)blockIdx.x + GRID - 1) / GRID;
    const int NGC   = ntile * NCHUNK;

    auto issue = [&](int gc) {
        int tile = (int)blockIdx.x + (gc >> 3) * GRID;
        int m0 = tile * BLOCK_M;
        int d0 = (gc & 7) * KC;
        int* dstbuf = (gc & 1) ? A_s1 : A_s0;
        #pragma unroll
        for (int i = 0; i < 8; i++) {
            int id = tid + i * 256;
            int dl = id >> 5, m4 = id & 31;
            const int4* src = (const int4*)(X2 + (size_t)(d0 + dl) * MPTS + m0) + m4;
            uint32_t dst = (uint32_t)__cvta_generic_to_shared(dstbuf + dl * ASTRIDE + m4 * 4);
            asm volatile("cp.async.cg.shared.global [%0], [%1], 16;\n" :: "r"(dst), "l"(src));
        }
        asm volatile("cp.async.commit_group;\n" ::: "memory");
    };

    float acc[2][4][4];

    issue(0);
    for (int gc = 0; gc < NGC; gc++) {
        if (gc + 1 < NGC) {
            issue(gc + 1);
            asm volatile("cp.async.wait_group 1;\n" ::: "memory");
        } else {
            asm volatile("cp.async.wait_group 0;\n" ::: "memory");
        }
        __syncthreads();

        const int c = gc & 7;
        if (c == 0) {
            #pragma unroll
            for (int mt = 0; mt < 2; mt++)
                #pragma unroll
                for (int nt = 0; nt < 4; nt++)
                    #pragma unroll
                    for (int i = 0; i < 4; i++) acc[mt][nt][i] = 0.f;
        }

        const int* Ab = (gc & 1) ? A_s1 : A_s0;
        #pragma unroll
        for (int ks = 0; ks < 4; ks++) {
            uint32_t a[2][4];
            #pragma unroll
            for (int mt = 0; mt < 2; mt++) {
                int m = wm * 32 + mt * 16 + g;
                #pragma unroll
                for (int q = 0; q < 4; q++) {
                    // a[0]=(r,k), a[1]=(r+8,k), a[2]=(r,k+8), a[3]=(r+8,k+8)
                    int kq  = ks * 16 + 2 * tig + (q >> 1) * 8;
                    int row = m + (q & 1) * 8;
                    uint32_t x0 = (uint32_t)Ab[kq * ASTRIDE + row];
                    uint32_t x1 = (uint32_t)Ab[(kq + 1) * ASTRIDE + row];
                    a[mt][q] = x0 * 0x3F80u + x1 * 0x3F800000u;   // bf16x2(lo=k, hi=k+1)
                }
            }
            int kglob = c * KC + ks * 16 + 2 * tig;
            uint32_t bfr[4][2];
            #pragma unroll
            for (int nt = 0; nt < 4; nt++) {
                int n = wb * 32 + nt * 8 + g;
                const uint32_t* vp = (const uint32_t*)(V_s + n * VSTRIDE + kglob);
                bfr[nt][0] = vp[0];   // k, k+1
                bfr[nt][1] = vp[4];   // k+8, k+9
            }
            #pragma unroll
            for (int mt = 0; mt < 2; mt++)
                #pragma unroll
                for (int nt = 0; nt < 4; nt++)
                    mma_bf16(acc[mt][nt], a[mt], bfr[nt]);
        }

        if (c == NCHUNK - 1) {
            // epilogue: WHD -> F -> *Y, reduce over this tile's 128 m rows
            int tile = (int)blockIdx.x + (gc >> 3) * GRID;
            int m0 = tile * BLOCK_M;
            float p[4][2];
            #pragma unroll
            for (int nt = 0; nt < 4; nt++) { p[nt][0] = 0.f; p[nt][1] = 0.f; }
            #pragma unroll
            for (int mt = 0; mt < 2; mt++) {
                int mg = m0 + wm * 32 + mt * 16 + g;
                float y0 = Y[mg], y1 = Y[mg + 8];
                #pragma unroll
                for (int nt = 0; nt < 4; nt++) {
                    int bc = wb * 32 + nt * 8 + 2 * tig;
                    float s0 = s1_s[bc], s1v = s1_s[bc + 1];
                    float f00 = squashF(1.f - (s0  + acc[mt][nt][0]) * inv_norm, kk, jj);
                    float f01 = squashF(1.f - (s1v + acc[mt][nt][1]) * inv_norm, kk, jj);
                    float f10 = squashF(1.f - (s0  + acc[mt][nt][2]) * inv_norm, kk, jj);
                    float f11 = squashF(1.f - (s1v + acc[mt][nt][3]) * inv_norm, kk, jj);
                    p[nt][0] += f00 * y0 + f10 * y1;
                    p[nt][1] += f01 * y0 + f11 * y1;
                }
            }
            #pragma unroll
            for (int nt = 0; nt < 4; nt++) {
                int bc = wb * 32 + nt * 8 + 2 * tig;
                atomicAdd(&s_acc[bc],     p[nt][0]);
                atomicAdd(&s_acc[bc + 1], p[nt][1]);
            }
        }
        __syncthreads();   // buffer (gc&1) reused by issue(gc+2) next iteration
    }

    if (tid < BQ) atomicAdd(&g_acc[tid], s_acc[tid]);
}

// -------------------- finalize --------------------
__global__ void knn_final(const float* __restrict__ alpha,
                          const float* __restrict__ beta,
                          float* __restrict__ out)
{
    int b = threadIdx.x;
    if (b < BQ)
        out[b] = beta[0] * (g_acc[b] * (1.0f / (float)MPTS) + alpha[0]);
}

// -------------------- launch --------------------
extern "C" void kernel_launch(void* const* d_in, const int* in_sizes, int n_in,
                              void* d_out, int out_size)
{
    const int*   X1    = (const int*)d_in[0];    // [512,64]
    const int*   X2    = (const int*)d_in[1];    // [512,131072]
    // d_in[2] (block-packed copy) unused
    const float* Y     = (const float*)d_in[3];  // [131072]
    const float* W     = (const float*)d_in[4];  // [512]
    const float* alpha = (const float*)d_in[5];
    const float* beta  = (const float*)d_in[6];
    const float* kp    = (const float*)d_in[7];
    const float* jp    = (const float*)d_in[8];
    float* out = (float*)d_out;

    int smem_bytes = BQ * VSTRIDE * 2 + 2 * KC * ASTRIDE * 4 + 2 * BQ * 4; // 134656
    cudaFuncSetAttribute(knn_main, cudaFuncAttributeMaxDynamicSharedMemorySize, smem_bytes);

    knn_prep<<<1, 256>>>(X1, W);
    knn_main<<<GRID, 256, smem_bytes>>>(X2, Y, kp, jp);
    knn_final<<<1, 64>>>(alpha, beta, out);
}

// round 8
// speedup vs baseline: 1.1980x; 1.1980x over previous
#include <cuda_runtime.h>
#include <cuda_bf16.h>
#include <cstdint>

#define DDIM    512
#define MPTS    131072
#define BQ      64
#define BLOCK_M 128
#define KC      64
#define NCHUNK  8                   // DDIM / KC
#define NTILES  (MPTS / BLOCK_M)    // 1024
#define GRID    148
#define NTH     512

#define VSTRIDE 520                 // bf16 per b-row (bank-safe for LDS + ldmatrix)
#define ASTRIDE 132                 // int32 per k-row (bank-safe, 16B rows)
#define VBYTES  (BQ * VSTRIDE * 2)          // 66560
#define ABYTES  (KC * ASTRIDE * 4)          // 33792
#define NSTAGE  3

// per-CTA partial results (no atomics, no pre-zero needed)
__device__ float g_part[GRID][BQ];

__device__ __forceinline__ float squashF(float x, float kk, float jj)
{
    float inner = x * (1.f - kk) / (kk * (1.f - 2.f * fabsf(x)) + 1.f);
    float t = 2.f * inner - 1.f;
    return 0.5f + 0.5f * t * (1.f + jj) / (-jj * (1.f - 2.f * fabsf(t)) + 1.f);
}

__device__ __forceinline__ void mma_bf16(float c[4], const uint32_t a[4],
                                         uint32_t b0, uint32_t b1)
{
    asm volatile(
        "mma.sync.aligned.m16n8k16.row.col.f32.bf16.bf16.f32 "
        "{%0,%1,%2,%3}, {%4,%5,%6,%7}, {%8,%9}, {%0,%1,%2,%3};\n"
        : "+f"(c[0]), "+f"(c[1]), "+f"(c[2]), "+f"(c[3])
        : "r"(a[0]), "r"(a[1]), "r"(a[2]), "r"(a[3]), "r"(b0), "r"(b1));
}

__global__ void __launch_bounds__(NTH, 1) knn_main(
    const int*   __restrict__ X1,   // [DDIM][BQ]
    const int*   __restrict__ X2,   // [DDIM][MPTS]
    const float* __restrict__ Y,    // [MPTS]
    const float* __restrict__ W,    // [DDIM]
    const float* __restrict__ kp,
    const float* __restrict__ jp)
{
    extern __shared__ char smem[];
    __nv_bfloat16* V_s = (__nv_bfloat16*)smem;
    char* Abase = smem + VBYTES;
    float* s1_s  = (float*)(smem + VBYTES + NSTAGE * ABYTES);
    float* s_acc = s1_s + BQ;
    float* nrm_s = s_acc + BQ;
    float* W_s   = (float*)Abase;   // overlay on A buffers, prologue only

    const int tid  = threadIdx.x;
    const int lane = tid & 31, warp = tid >> 5;
    const int g = lane >> 2, tig = lane & 3;
    const int wm = warp & 7, wb = warp >> 3;   // 8 m-strips(16) x 2 b-halves(32)

    // ---------------- prologue: V, s1, norm (per-CTA, redundant) ----------------
    W_s[tid] = W[tid];                         // NTH == DDIM
    if (tid < BQ) { s1_s[tid] = 0.f; s_acc[tid] = 0.f; }
    if (tid == 0) nrm_s[0] = 0.f;
    __syncthreads();

    {
        int b = tid & 63, part = tid >> 6;     // 8 parts of 64 d
        // V[b][d] = +-W[d]
        #pragma unroll 4
        for (int d = part; d < DDIM; d += 8) {
            float w = W_s[d];
            int x1 = X1[d * BQ + b];
            V_s[b * VSTRIDE + d] = __float2bfloat16(x1 ? -w : w);
        }
        // s1[b] partial (fp32 exact)
        float s = 0.f;
        #pragma unroll 4
        for (int d = part * 64; d < part * 64 + 64; d++)
            s += W_s[d] * (float)X1[d * BQ + b];
        atomicAdd(&s1_s[b], s);
        // norm
        float a = fabsf(W_s[tid]);
        #pragma unroll
        for (int o = 16; o; o >>= 1) a += __shfl_down_sync(0xffffffffu, a, o);
        if (lane == 0) atomicAdd(nrm_s, a);
    }
    __syncthreads();

    const float inv_norm = 1.f / (nrm_s[0] + 1e-6f);
    const float kk = kp[0], jj = jp[0];

    const int ntile = (NTILES - (int)blockIdx.x + GRID - 1) / GRID;
    const int NGC   = ntile * NCHUNK;

    // ldmatrix base address for B fragments (per-lane, constant across loop)
    const int mi = lane >> 3, r = lane & 7;     // matrix idx, row-in-matrix
    const int nt_a = mi >> 1, kh = mi & 1;      // first call: nt 0/1
    const uint32_t v_base = (uint32_t)__cvta_generic_to_shared(V_s);
    const uint32_t ldm0 = v_base + ((wb * 32 + nt_a * 8 + r) * VSTRIDE + kh * 8) * 2;
    const uint32_t ldm1 = ldm0 + 16 * VSTRIDE * 2;   // nt 2/3

    auto issue = [&](int gc) {
        int tile = (int)blockIdx.x + (gc >> 3) * GRID;
        int m0 = tile * BLOCK_M;
        int d0 = (gc & 7) * KC;
        char* dstbuf = Abase + (gc % NSTAGE) * ABYTES;
        #pragma unroll
        for (int i = 0; i < 4; i++) {
            int id = tid + i * NTH;            // 2048 16B copies
            int dl = id >> 5, m4 = id & 31;
            const int4* src = (const int4*)(X2 + (size_t)(d0 + dl) * MPTS + m0) + m4;
            uint32_t dst = (uint32_t)__cvta_generic_to_shared(
                (int*)dstbuf + dl * ASTRIDE + m4 * 4);
            asm volatile("cp.async.cg.shared.global [%0], [%1], 16;\n" :: "r"(dst), "l"(src));
        }
        asm volatile("cp.async.commit_group;\n" ::: "memory");
    };

    float acc[4][4];

    issue(0);
    issue(1);
    for (int gc = 0; gc < NGC; gc++) {
        if (gc + 2 < NGC) {
            issue(gc + 2);
            asm volatile("cp.async.wait_group 2;\n" ::: "memory");
        } else if (gc + 1 < NGC) {
            asm volatile("cp.async.wait_group 1;\n" ::: "memory");
        } else {
            asm volatile("cp.async.wait_group 0;\n" ::: "memory");
        }
        __syncthreads();

        const int c = gc & 7;
        if (c == 0) {
            #pragma unroll
            for (int nt = 0; nt < 4; nt++)
                #pragma unroll
                for (int i = 0; i < 4; i++) acc[nt][i] = 0.f;
        }

        const int* Ab = (const int*)(Abase + (gc % NSTAGE) * ABYTES);
        const int mrow = wm * 16 + g;
        #pragma unroll
        for (int ks = 0; ks < 4; ks++) {
            uint32_t a[4];
            #pragma unroll
            for (int q = 0; q < 4; q++) {
                int kq  = ks * 16 + 2 * tig + (q >> 1) * 8;
                int row = mrow + (q & 1) * 8;
                uint32_t x0 = (uint32_t)Ab[kq * ASTRIDE + row];
                uint32_t x1 = (uint32_t)Ab[(kq + 1) * ASTRIDE + row];
                a[q] = x0 * 0x3F80u + x1 * 0x3F800000u;   // bf16x2 (k, k+1)
            }
            uint32_t koff = (uint32_t)((c * KC + ks * 16) * 2);
            uint32_t b01[4], b23[4];
            asm volatile(
                "ldmatrix.sync.aligned.m8n8.x4.shared.b16 {%0,%1,%2,%3}, [%4];\n"
                : "=r"(b01[0]), "=r"(b01[1]), "=r"(b01[2]), "=r"(b01[3])
                : "r"(ldm0 + koff));
            asm volatile(
                "ldmatrix.sync.aligned.m8n8.x4.shared.b16 {%0,%1,%2,%3}, [%4];\n"
                : "=r"(b23[0]), "=r"(b23[1]), "=r"(b23[2]), "=r"(b23[3])
                : "r"(ldm1 + koff));
            mma_bf16(acc[0], a, b01[0], b01[1]);
            mma_bf16(acc[1], a, b01[2], b01[3]);
            mma_bf16(acc[2], a, b23[0], b23[1]);
            mma_bf16(acc[3], a, b23[2], b23[3]);
        }

        if (c == NCHUNK - 1) {
            int tile = (int)blockIdx.x + (gc >> 3) * GRID;
            int mg = tile * BLOCK_M + wm * 16 + g;
            float y0 = Y[mg], y1 = Y[mg + 8];
            #pragma unroll
            for (int nt = 0; nt < 4; nt++) {
                int bc = wb * 32 + nt * 8 + 2 * tig;
                float s0 = s1_s[bc], s1v = s1_s[bc + 1];
                float f00 = squashF(1.f - (s0  + acc[nt][0]) * inv_norm, kk, jj);
                float f01 = squashF(1.f - (s1v + acc[nt][1]) * inv_norm, kk, jj);
                float f10 = squashF(1.f - (s0  + acc[nt][2]) * inv_norm, kk, jj);
                float f11 = squashF(1.f - (s1v + acc[nt][3]) * inv_norm, kk, jj);
                atomicAdd(&s_acc[bc],     f00 * y0 + f10 * y1);
                atomicAdd(&s_acc[bc + 1], f01 * y0 + f11 * y1);
            }
        }
        __syncthreads();   // buffer gc%NSTAGE reused by issue(gc+3)
    }

    if (tid < BQ) g_part[blockIdx.x][tid] = s_acc[tid];
}

// -------------------- finalize: sum per-CTA partials --------------------
__global__ void knn_final(const float* __restrict__ alpha,
                          const float* __restrict__ beta,
                          float* __restrict__ out)
{
    __shared__ float red[4][BQ];
    int b = threadIdx.x & 63, part = threadIdx.x >> 6;   // 256 threads
    float s = 0.f;
    for (int i = part; i < GRID; i += 4) s += g_part[i][b];
    red[part][b] = s;
    __syncthreads();
    if (threadIdx.x < BQ) {
        float t = red[0][b] + red[1][b] + red[2][b] + red[3][b];
        out[b] = beta[0] * (t * (1.0f / (float)MPTS) + alpha[0]);
    }
}

// -------------------- launch --------------------
extern "C" void kernel_launch(void* const* d_in, const int* in_sizes, int n_in,
                              void* d_out, int out_size)
{
    const int*   X1    = (const int*)d_in[0];    // [512,64]
    const int*   X2    = (const int*)d_in[1];    // [512,131072]
    const float* Y     = (const float*)d_in[3];  // [131072]
    const float* W     = (const float*)d_in[4];  // [512]
    const float* alpha = (const float*)d_in[5];
    const float* beta  = (const float*)d_in[6];
    const float* kp    = (const float*)d_in[7];
    const float* jp    = (const float*)d_in[8];
    float* out = (float*)d_out;

    int smem_bytes = VBYTES + NSTAGE * ABYTES + (2 * BQ + 1) * 4 + 64;  // ~168.6 KB
    cudaFuncSetAttribute(knn_main, cudaFuncAttributeMaxDynamicSharedMemorySize, smem_bytes);

    knn_main<<<GRID, NTH, smem_bytes>>>(X1, X2, Y, W, kp, jp);
    knn_final<<<1, 256>>>(alpha, beta, out);
}

// round 11
// speedup vs baseline: 2.4364x; 2.0338x over previous
#include <cuda_runtime.h>
#include <cuda_bf16.h>
#include <cstdint>

#define DDIM    512
#define MPTS    131072
#define BQ      64
#define STRIP_M 16
#define NSTRIPS (MPTS / STRIP_M)    // 8192
#define GRID    148
#define NTH     512
#define NWARPS  (GRID * NTH / 32)   // 2368

#define VSTRIDE 520                 // bf16 per n-row (bank-safe, proven R8)
#define VBYTES  (BQ * VSTRIDE * 2)  // 66560
// control block after V
#define S1_OFF   VBYTES
#define SA_OFF   (VBYTES + 256)
#define NRM_OFF  (VBYTES + 512)
#define WS_OFF   (VBYTES + 576)
#define SMEM_TOTAL (WS_OFF + DDIM * 4)

__device__ float g_part[GRID][BQ];

__device__ __forceinline__ float squashF(float x, float kk, float jj)
{
    float inner = x * (1.f - kk) * __fdividef(1.f, kk * (1.f - 2.f * fabsf(x)) + 1.f);
    float t = 2.f * inner - 1.f;
    return 0.5f + 0.5f * t * (1.f + jj) * __fdividef(1.f, -jj * (1.f - 2.f * fabsf(t)) + 1.f);
}

__device__ __forceinline__ void mma_bf16(float c[4], const uint32_t a[4],
                                         uint32_t b0, uint32_t b1)
{
    asm volatile(
        "mma.sync.aligned.m16n8k16.row.col.f32.bf16.bf16.f32 "
        "{%0,%1,%2,%3}, {%4,%5,%6,%7}, {%8,%9}, {%0,%1,%2,%3};\n"
        : "+f"(c[0]), "+f"(c[1]), "+f"(c[2]), "+f"(c[3])
        : "r"(a[0]), "r"(a[1]), "r"(a[2]), "r"(a[3]), "r"(b0), "r"(b1));
}

// 8 raw int32 loads for one k16 step; layout matches A-fragment q-mapping
__device__ __forceinline__ void ld8(int r[8], const int* __restrict__ p)
{
    r[0] = __ldcs(p);
    r[1] = __ldcs(p + MPTS);
    r[2] = __ldcs(p + 8);
    r[3] = __ldcs(p + MPTS + 8);
    r[4] = __ldcs(p + 8 * MPTS);
    r[5] = __ldcs(p + 9 * MPTS);
    r[6] = __ldcs(p + 8 * MPTS + 8);
    r[7] = __ldcs(p + 9 * MPTS + 8);
}

__device__ __forceinline__ void pack4(uint32_t a[4], const int r[8])
{
    a[0] = (uint32_t)r[0] * 0x3F80u + (uint32_t)r[1] * 0x3F800000u;
    a[1] = (uint32_t)r[2] * 0x3F80u + (uint32_t)r[3] * 0x3F800000u;
    a[2] = (uint32_t)r[4] * 0x3F80u + (uint32_t)r[5] * 0x3F800000u;
    a[3] = (uint32_t)r[6] * 0x3F80u + (uint32_t)r[7] * 0x3F800000u;
}

__global__ void __launch_bounds__(NTH, 1) knn_main(
    const int*   __restrict__ X1,   // [DDIM][BQ]
    const int*   __restrict__ X2,   // [DDIM][MPTS]
    const float* __restrict__ Y,    // [MPTS]
    const float* __restrict__ W,    // [DDIM]
    const float* __restrict__ kp,
    const float* __restrict__ jp)
{
    extern __shared__ char smem[];
    __nv_bfloat16* V_s = (__nv_bfloat16*)smem;
    float* s1_s  = (float*)(smem + S1_OFF);
    float* s_acc = (float*)(smem + SA_OFF);
    float* nrm_s = (float*)(smem + NRM_OFF);
    float* W_s   = (float*)(smem + WS_OFF);

    const int tid  = threadIdx.x;
    const int lane = tid & 31, warp = tid >> 5;
    const int g = lane >> 2, tig = lane & 3;

    // ---------------- prologue: V, s1, norm (verbatim from passing R8) ----------------
    W_s[tid] = W[tid];
    if (tid < BQ) { s1_s[tid] = 0.f; s_acc[tid] = 0.f; }
    if (tid == 0) nrm_s[0] = 0.f;
    __syncthreads();
    {
        int b = tid & 63, part = tid >> 6;     // 8 parts of 64 d
        #pragma unroll 4
        for (int d = part; d < DDIM; d += 8) {
            float w = W_s[d];
            int x1 = X1[d * BQ + b];
            V_s[b * VSTRIDE + d] = __float2bfloat16(x1 ? -w : w);
        }
        float s = 0.f;
        #pragma unroll 4
        for (int d = part * 64; d < part * 64 + 64; d++)
            s += W_s[d] * (float)X1[d * BQ + b];
        atomicAdd(&s1_s[b], s);
        float a = fabsf(W_s[tid]);
        #pragma unroll
        for (int o = 16; o; o >>= 1) a += __shfl_down_sync(0xffffffffu, a, o);
        if (lane == 0) atomicAdd(nrm_s, a);
    }
    __syncthreads();

    const float inv_norm = __fdividef(1.f, nrm_s[0] + 1e-6f);
    const float kk = kp[0], jj = jp[0];

    // B ldmatrix lane addressing (proven R8 pattern, extended to 4 n-blocks)
    const int mi = lane >> 3, r8 = lane & 7;
    const int nt_a = mi >> 1, kh = mi & 1;
    const uint32_t v_base = (uint32_t)__cvta_generic_to_shared(V_s);
    uint32_t ldm[4];
    #pragma unroll
    for (int nb = 0; nb < 4; nb++)
        ldm[nb] = v_base + (uint32_t)(((nb * 16 + nt_a * 8 + r8) * VSTRIDE + kh * 8) * 2);

    const int gw = (int)blockIdx.x * (NTH / 32) + warp;   // global warp id

    float sc[16];
    #pragma unroll
    for (int i = 0; i < 16; i++) sc[i] = 0.f;

    for (int strip = gw; strip < NSTRIPS; strip += NWARPS) {
        const int m0 = strip * STRIP_M;
        float acc[8][4];
        #pragma unroll
        for (int nf = 0; nf < 8; nf++)
            #pragma unroll
            for (int i = 0; i < 4; i++) acc[nf][i] = 0.f;

        const int* pb = X2 + (size_t)(2 * tig) * MPTS + m0 + g;
        int ra[8], rb[8];
        ld8(ra, pb);
        ld8(rb, pb + (size_t)16 * MPTS);

        #pragma unroll
        for (int s = 0; s < 32; s += 2) {
            uint32_t a[4];
            // ---- step s (from ra) ----
            pack4(a, ra);
            if (s + 2 < 32) ld8(ra, pb + (size_t)(s + 2) * 16 * MPTS);
            {
                uint32_t koff = (uint32_t)(s * 32);
                #pragma unroll
                for (int nb = 0; nb < 4; nb++) {
                    uint32_t b[4];
                    asm volatile(
                        "ldmatrix.sync.aligned.m8n8.x4.shared.b16 {%0,%1,%2,%3}, [%4];\n"
                        : "=r"(b[0]), "=r"(b[1]), "=r"(b[2]), "=r"(b[3])
                        : "r"(ldm[nb] + koff));
                    mma_bf16(acc[2 * nb],     a, b[0], b[1]);
                    mma_bf16(acc[2 * nb + 1], a, b[2], b[3]);
                }
            }
            // ---- step s+1 (from rb) ----
            pack4(a, rb);
            if (s + 3 < 32) ld8(rb, pb + (size_t)(s + 3) * 16 * MPTS);
            {
                uint32_t koff = (uint32_t)((s + 1) * 32);
                #pragma unroll
                for (int nb = 0; nb < 4; nb++) {
                    uint32_t b[4];
                    asm volatile(
                        "ldmatrix.sync.aligned.m8n8.x4.shared.b16 {%0,%1,%2,%3}, [%4];\n"
                        : "=r"(b[0]), "=r"(b[1]), "=r"(b[2]), "=r"(b[3])
                        : "r"(ldm[nb] + koff));
                    mma_bf16(acc[2 * nb],     a, b[0], b[1]);
                    mma_bf16(acc[2 * nb + 1], a, b[2], b[3]);
                }
            }
        }

        // ---- fused epilogue for this strip ----
        float y0 = __ldg(Y + m0 + g);
        float y1 = __ldg(Y + m0 + 8 + g);
        #pragma unroll
        for (int nf = 0; nf < 8; nf++) {
            int c0 = nf * 8 + 2 * tig;
            float s1a = s1_s[c0], s1b = s1_s[c0 + 1];
            float f00 = squashF(1.f - (s1a + acc[nf][0]) * inv_norm, kk, jj);
            float f01 = squashF(1.f - (s1b + acc[nf][1]) * inv_norm, kk, jj);
            float f10 = squashF(1.f - (s1a + acc[nf][2]) * inv_norm, kk, jj);
            float f11 = squashF(1.f - (s1b + acc[nf][3]) * inv_norm, kk, jj);
            sc[2 * nf]     += f00 * y0 + f10 * y1;
            sc[2 * nf + 1] += f01 * y0 + f11 * y1;
        }
    }

    // ---- reduce sc over the 8 g-lanes sharing each column set ----
    #pragma unroll
    for (int i = 0; i < 16; i++) {
        float v = sc[i];
        v += __shfl_down_sync(0xffffffffu, v, 16);
        v += __shfl_down_sync(0xffffffffu, v, 8);
        v += __shfl_down_sync(0xffffffffu, v, 4);
        if (lane < 4) {
            int col = (i >> 1) * 8 + 2 * lane + (i & 1);
            atomicAdd(&s_acc[col], v);
        }
    }
    __syncthreads();
    if (tid < BQ) g_part[blockIdx.x][tid] = s_acc[tid];
}

// -------------------- finalize --------------------
__global__ void knn_final(const float* __restrict__ alpha,
                          const float* __restrict__ beta,
                          float* __restrict__ out)
{
    __shared__ float red[4][BQ];
    int b = threadIdx.x & 63, part = threadIdx.x >> 6;   // 256 threads
    float s = 0.f;
    for (int i = part; i < GRID; i += 4) s += g_part[i][b];
    red[part][b] = s;
    __syncthreads();
    if (threadIdx.x < BQ) {
        float t = red[0][b] + red[1][b] + red[2][b] + red[3][b];
        out[b] = beta[0] * (t * (1.0f / (float)MPTS) + alpha[0]);
    }
}

// -------------------- launch --------------------
extern "C" void kernel_launch(void* const* d_in, const int* in_sizes, int n_in,
                              void* d_out, int out_size)
{
    const int*   X1    = (const int*)d_in[0];    // [512,64]
    const int*   X2    = (const int*)d_in[1];    // [512,131072]
    const float* Y     = (const float*)d_in[3];  // [131072]
    const float* W     = (const float*)d_in[4];  // [512]
    const float* alpha = (const float*)d_in[5];
    const float* beta  = (const float*)d_in[6];
    const float* kp    = (const float*)d_in[7];
    const float* jp    = (const float*)d_in[8];
    float* out = (float*)d_out;

    cudaFuncSetAttribute(knn_main, cudaFuncAttributeMaxDynamicSharedMemorySize, SMEM_TOTAL);

    knn_main<<<GRID, NTH, SMEM_TOTAL>>>(X1, X2, Y, W, kp, jp);
    knn_final<<<1, 256>>>(alpha, beta, out);
}